// round 1
// baseline (speedup 1.0000x reference)
#include <cuda_runtime.h>
#include <math.h>

// Problem constants
#define Bq   2
#define Sq   1024
#define Dq   512
#define Fq   2048
#define MF   (Bq*Sq)          // 2048 GEMM rows
#define FLAT (Sq*Dq)          // 524288 per-batch flat size (2^19)
#define TOT  (Bq*FLAT)        // 1048576
#define LAMv 1e-4f

// ---------------- scratch (no allocations allowed) ----------------
__device__ float g_xb[(size_t)MF*Fq];   // x@Wx + b1 (16MB)
__device__ float g_h [(size_t)MF*Fq];   // hidden (16MB)
__device__ float g_z [TOT];             // current z
__device__ float g_f [TOT];             // f(z)
__device__ float g_Gh[4][TOT];          // g history, circular (16MB)
__device__ float g_Zh[4][TOT];          // z history, circular (16MB)
__device__ float g_red[2*14];           // per-batch: 10 HTH (upper tri) + 4 HTy
__device__ float g_gamma[2*4];

// ---------------- GEMM: C = act(A@B + bias/D) ----------------
// MODE 0: C[m][n] = acc + bias[n]
// MODE 1: C[m][n] = tanhf(acc + D[m][n])
template<int BM, int BN, int BK, int TM, int TN, int MODE>
__global__ __launch_bounds__(256) void gemm_k(
    const float* __restrict__ A, const float* __restrict__ B,
    const float* __restrict__ bias, const float* __restrict__ Dm,
    float* __restrict__ C, int M, int N, int K)
{
    __shared__ float As[BK][BM + 4];   // +4 pad keeps float4 alignment, reduces store conflicts
    __shared__ float Bs[BK][BN];

    const int tid = threadIdx.x;
    const int tx  = tid % (BN / TN);
    const int ty  = tid / (BN / TN);
    const int bx  = blockIdx.x, by = blockIdx.y;

    float acc[TM][TN];
#pragma unroll
    for (int i = 0; i < TM; i++)
#pragma unroll
        for (int j = 0; j < TN; j++) acc[i][j] = 0.f;

    const float* Ab = A + (size_t)by * BM * K;
    const float* Bb = B + (size_t)bx * BN;

    for (int kt = 0; kt < K; kt += BK) {
        // load A tile (BM x BK), stored transposed
#pragma unroll
        for (int l = tid; l < BM * BK / 4; l += 256) {
            int ar = l / (BK / 4);
            int ac = (l % (BK / 4)) * 4;
            float4 v = *(const float4*)(Ab + (size_t)ar * K + kt + ac);
            As[ac + 0][ar] = v.x; As[ac + 1][ar] = v.y;
            As[ac + 2][ar] = v.z; As[ac + 3][ar] = v.w;
        }
        // load B tile (BK x BN)
#pragma unroll
        for (int l = tid; l < BK * BN / 4; l += 256) {
            int br = l / (BN / 4);
            int bc = (l % (BN / 4)) * 4;
            *(float4*)&Bs[br][bc] = *(const float4*)(Bb + (size_t)(kt + br) * N + bc);
        }
        __syncthreads();

#pragma unroll
        for (int k = 0; k < BK; k++) {
            float a[TM], b[TN];
#pragma unroll
            for (int i = 0; i < TM; i += 4) *(float4*)&a[i] = *(float4*)&As[k][ty * TM + i];
#pragma unroll
            for (int j = 0; j < TN; j += 4) *(float4*)&b[j] = *(float4*)&Bs[k][tx * TN + j];
#pragma unroll
            for (int i = 0; i < TM; i++)
#pragma unroll
                for (int j = 0; j < TN; j++)
                    acc[i][j] = fmaf(a[i], b[j], acc[i][j]);
        }
        __syncthreads();
    }

    // epilogue
#pragma unroll
    for (int i = 0; i < TM; i++) {
        int gm = by * BM + ty * TM + i;
#pragma unroll
        for (int j = 0; j < TN; j += 4) {
            int gn = bx * BN + tx * TN + j;
            float4 r;
            if (MODE == 0) {
                r.x = acc[i][j]     + bias[gn];
                r.y = acc[i][j + 1] + bias[gn + 1];
                r.z = acc[i][j + 2] + bias[gn + 2];
                r.w = acc[i][j + 3] + bias[gn + 3];
            } else {
                const float* dptr = Dm + (size_t)gm * N + gn;
                r.x = tanhf(acc[i][j]     + dptr[0]);
                r.y = tanhf(acc[i][j + 1] + dptr[1]);
                r.z = tanhf(acc[i][j + 2] + dptr[2]);
                r.w = tanhf(acc[i][j + 3] + dptr[3]);
            }
            *(float4*)(C + (size_t)gm * N + gn) = r;
        }
    }
}

// ---------------- iteration 0: h = tanh(xb) (z==0, skip GEMM1) ----------------
__global__ void tanh_map(const float* __restrict__ src, float* __restrict__ dst)
{
    int i = blockIdx.x * blockDim.x + threadIdx.x;
    float4 v = ((const float4*)src)[i];
    v.x = tanhf(v.x); v.y = tanhf(v.y); v.z = tanhf(v.z); v.w = tanhf(v.w);
    ((float4*)dst)[i] = v;
}

// ---------------- i < M: z_new = f; record history ----------------
__global__ void upd_simple(const float* __restrict__ f, float* __restrict__ z,
                           float* __restrict__ dst, int sw)
{
    int i = blockIdx.x * blockDim.x + threadIdx.x;   // float4 index over TOT/4
    float4 fv = ((const float4*)f)[i];
    float4 zv = ((const float4*)z)[i];
    float4 gv;
    gv.x = fv.x - zv.x; gv.y = fv.y - zv.y; gv.z = fv.z - zv.z; gv.w = fv.w - zv.w;
    ((float4*)g_Gh[sw])[i] = gv;
    ((float4*)g_Zh[sw])[i] = zv;
    ((float4*)dst)[i] = fv;
}

// ---------------- Anderson: HTH/HTy reduction ----------------
__global__ void reduce_k(const float* __restrict__ f, const float* __restrict__ z,
                         int s1, int s2, int s3, int s4)
{
    int b = blockIdx.y;
    int base = b * (FLAT / 4);
    const float4* fp = (const float4*)f + base;
    const float4* zp = (const float4*)z + base;
    const float4* h1 = (const float4*)g_Gh[s1] + base;
    const float4* h2 = (const float4*)g_Gh[s2] + base;
    const float4* h3 = (const float4*)g_Gh[s3] + base;
    const float4* h4 = (const float4*)g_Gh[s4] + base;

    float acc[14];
#pragma unroll
    for (int v = 0; v < 14; v++) acc[v] = 0.f;

    int n4 = FLAT / 4;
    for (int i = blockIdx.x * blockDim.x + threadIdx.x; i < n4;
         i += gridDim.x * blockDim.x) {
        float4 fv = fp[i], zv = zp[i];
        float4 a1 = h1[i], a2 = h2[i], a3 = h3[i], a4 = h4[i];
        const float* fa = (const float*)&fv; const float* za = (const float*)&zv;
        const float* p1 = (const float*)&a1; const float* p2 = (const float*)&a2;
        const float* p3 = (const float*)&a3; const float* p4 = (const float*)&a4;
#pragma unroll
        for (int c = 0; c < 4; c++) {
            float g  = fa[c] - za[c];
            float d0 = g - p1[c];
            float d1 = g - p2[c];
            float d2 = g - p3[c];
            float d3 = g - p4[c];
            acc[0] += d0 * d0; acc[1] += d0 * d1; acc[2] += d0 * d2; acc[3] += d0 * d3;
            acc[4] += d1 * d1; acc[5] += d1 * d2; acc[6] += d1 * d3;
            acc[7] += d2 * d2; acc[8] += d2 * d3; acc[9] += d3 * d3;
            acc[10] += d0 * g; acc[11] += d1 * g; acc[12] += d2 * g; acc[13] += d3 * g;
        }
    }
    // warp reduce
#pragma unroll
    for (int v = 0; v < 14; v++)
#pragma unroll
        for (int o = 16; o > 0; o >>= 1)
            acc[v] += __shfl_down_sync(0xffffffffu, acc[v], o);

    __shared__ float sm[8][14];
    int w = threadIdx.x / 32, lane = threadIdx.x % 32;
    if (lane == 0) {
#pragma unroll
        for (int v = 0; v < 14; v++) sm[w][v] = acc[v];
    }
    __syncthreads();
    if (threadIdx.x < 14) {
        float s = 0.f;
#pragma unroll
        for (int w2 = 0; w2 < 8; w2++) s += sm[w2][threadIdx.x];
        atomicAdd(&g_red[b * 14 + threadIdx.x], s);
    }
}

// ---------------- 4x4 Schur-complement solve (replicates reference exactly) ----------------
__device__ __forceinline__ void inv2x2d(const float m[4], float o[4])
{
    float invDet = 1.f / (m[0] * m[3] - m[1] * m[2] + 1e-6f);
    o[0] =  m[3] * invDet; o[1] = -m[1] * invDet;
    o[2] = -m[2] * invDet; o[3] =  m[0] * invDet;
}
__device__ __forceinline__ void mul2x2d(const float a[4], const float b[4], float o[4])
{
    o[0] = a[0] * b[0] + a[1] * b[2]; o[1] = a[0] * b[1] + a[1] * b[3];
    o[2] = a[2] * b[0] + a[3] * b[2]; o[3] = a[2] * b[1] + a[3] * b[3];
}

__global__ void solve_k()
{
    int b = threadIdx.x;
    if (b >= 2) return;
    const float* r = &g_red[b * 14];
    float H[4][4];
    H[0][0] = r[0] + LAMv; H[0][1] = r[1];        H[0][2] = r[2];        H[0][3] = r[3];
    H[1][0] = r[1];        H[1][1] = r[4] + LAMv; H[1][2] = r[5];        H[1][3] = r[6];
    H[2][0] = r[2];        H[2][1] = r[5];        H[2][2] = r[7] + LAMv; H[2][3] = r[8];
    H[3][0] = r[3];        H[3][1] = r[6];        H[3][2] = r[8];        H[3][3] = r[9] + LAMv;
    float y[4] = { r[10], r[11], r[12], r[13] };

    float A_[4] = { H[0][0], H[0][1], H[1][0], H[1][1] };
    float Bb[4] = { H[0][2], H[0][3], H[1][2], H[1][3] };
    float C_[4] = { H[2][0], H[2][1], H[3][0], H[3][1] };
    float Dd[4] = { H[2][2], H[2][3], H[3][2], H[3][3] };

    float Ai[4];   inv2x2d(A_, Ai);
    float CAi[4];  mul2x2d(C_, Ai, CAi);
    float CAiB[4]; mul2x2d(CAi, Bb, CAiB);
    float Sch[4]  = { Dd[0] - CAiB[0], Dd[1] - CAiB[1], Dd[2] - CAiB[2], Dd[3] - CAiB[3] };
    float Si[4];   inv2x2d(Sch, Si);
    float SiCAi[4]; mul2x2d(Si, CAi, SiCAi);
    float AiB[4];   mul2x2d(Ai, Bb, AiB);
    float t11[4];   mul2x2d(AiB, SiCAi, t11);
    float b11[4] = { Ai[0] + t11[0], Ai[1] + t11[1], Ai[2] + t11[2], Ai[3] + t11[3] };
    float b12[4];   mul2x2d(AiB, Si, b12);
    b12[0] = -b12[0]; b12[1] = -b12[1]; b12[2] = -b12[2]; b12[3] = -b12[3];

    float inv[4][4] = {
        { b11[0],  b11[1],  b12[0],  b12[1] },
        { b11[2],  b11[3],  b12[2],  b12[3] },
        { -SiCAi[0], -SiCAi[1], Si[0], Si[1] },
        { -SiCAi[2], -SiCAi[3], Si[2], Si[3] }
    };
#pragma unroll
    for (int j = 0; j < 4; j++)
        g_gamma[b * 4 + j] = inv[j][0] * y[0] + inv[j][1] * y[1]
                           + inv[j][2] * y[2] + inv[j][3] * y[3];
}

// ---------------- Anderson mixed update ----------------
__global__ void upd_anderson(const float* __restrict__ f, float* __restrict__ z,
                             float* __restrict__ dst,
                             int s1, int s2, int s3, int s4, int sw)
{
    int i = blockIdx.x * blockDim.x + threadIdx.x;   // float4 index over TOT/4
    int b = i >> 17;                                 // (i*4) / FLAT, FLAT = 2^19
    float ga0 = g_gamma[b * 4 + 0];
    float ga1 = g_gamma[b * 4 + 1];
    float ga2 = g_gamma[b * 4 + 2];
    float ga3 = g_gamma[b * 4 + 3];

    float4 fv = ((const float4*)f)[i];
    float4 zv = ((const float4*)z)[i];
    float4 G1 = ((const float4*)g_Gh[s1])[i];
    float4 G2 = ((const float4*)g_Gh[s2])[i];
    float4 G3 = ((const float4*)g_Gh[s3])[i];
    float4 G4 = ((const float4*)g_Gh[s4])[i];
    float4 Z1 = ((const float4*)g_Zh[s1])[i];
    float4 Z2 = ((const float4*)g_Zh[s2])[i];
    float4 Z3 = ((const float4*)g_Zh[s3])[i];
    float4 Z4 = ((const float4*)g_Zh[s4])[i];

    float4 gv, ov;
    float* fa = (float*)&fv;  float* za = (float*)&zv;
    float* g1 = (float*)&G1;  float* g2 = (float*)&G2;
    float* g3 = (float*)&G3;  float* g4 = (float*)&G4;
    float* z1 = (float*)&Z1;  float* z2 = (float*)&Z2;
    float* z3 = (float*)&Z3;  float* z4 = (float*)&Z4;
    float* gva = (float*)&gv; float* ova = (float*)&ov;

#pragma unroll
    for (int c = 0; c < 4; c++) {
        float zc = za[c];
        float g  = fa[c] - zc;
        float corr = ga0 * ((zc - z1[c]) + (g - g1[c]))
                   + ga1 * ((zc - z2[c]) + (g - g2[c]))
                   + ga2 * ((zc - z3[c]) + (g - g3[c]))
                   + ga3 * ((zc - z4[c]) + (g - g4[c]));
        gva[c] = g;
        ova[c] = zc + g - corr;
    }
    ((float4*)g_Gh[sw])[i] = gv;   // sw == s4: old slot already consumed above
    ((float4*)g_Zh[sw])[i] = zv;
    ((float4*)dst)[i] = ov;
}

// ---------------- launcher ----------------
extern "C" void kernel_launch(void* const* d_in, const int* in_sizes, int n_in,
                              void* d_out, int out_size)
{
    (void)in_sizes; (void)n_in; (void)out_size;
    const float* x  = (const float*)d_in[0];
    const float* W1 = (const float*)d_in[1];
    const float* Wx = (const float*)d_in[2];
    const float* b1 = (const float*)d_in[3];
    const float* W2 = (const float*)d_in[4];
    const float* b2 = (const float*)d_in[5];
    float* out = (float*)d_out;

    float *xb, *h, *z, *f, *red;
    cudaGetSymbolAddress((void**)&xb,  g_xb);
    cudaGetSymbolAddress((void**)&h,   g_h);
    cudaGetSymbolAddress((void**)&z,   g_z);
    cudaGetSymbolAddress((void**)&f,   g_f);
    cudaGetSymbolAddress((void**)&red, g_red);

    cudaMemsetAsync(z, 0, (size_t)TOT * sizeof(float));

    dim3 gbig(Fq / 128, MF / 128);   // 16 x 16 blocks, N=2048
    dim3 gsm (Dq / 64,  MF / 64);    // 8 x 32 blocks,  N=512

    // xb = x @ Wx + b1   (once)
    gemm_k<128, 128, 16, 8, 8, 0><<<gbig, 256>>>(x, Wx, b1, nullptr, xb, MF, Fq, Dq);

    const int upd_blocks = TOT / 4 / 256;   // 1024
    for (int i = 0; i < 12; i++) {
        // h = tanh(z @ W1 + xb)
        if (i == 0)
            tanh_map<<<(size_t)MF * Fq / 4 / 256, 256>>>(xb, h);   // z == 0
        else
            gemm_k<128, 128, 16, 8, 8, 1><<<gbig, 256>>>(z, W1, nullptr, xb, h, MF, Fq, Dq);
        // f = h @ W2 + b2
        gemm_k<64, 64, 16, 4, 4, 0><<<gsm, 256>>>(h, W2, b2, nullptr, f, MF, Dq, Fq);

        float* dst = (i == 11) ? out : z;
        if (i < 5) {
            upd_simple<<<upd_blocks, 256>>>(f, z, dst, i & 3);
        } else {
            cudaMemsetAsync(red, 0, 28 * sizeof(float));
            reduce_k<<<dim3(128, 2), 256>>>(f, z, (i - 1) & 3, (i - 2) & 3,
                                            (i - 3) & 3, (i - 4) & 3);
            solve_k<<<1, 32>>>();
            upd_anderson<<<upd_blocks, 256>>>(f, z, dst, (i - 1) & 3, (i - 2) & 3,
                                              (i - 3) & 3, (i - 4) & 3, i & 3);
        }
    }
}

// round 4
// speedup vs baseline: 1.7868x; 1.7868x over previous
#include <cuda_runtime.h>
#include <cuda_bf16.h>
#include <math.h>
#include <stdint.h>

// Problem constants
#define Bq   2
#define Sq   1024
#define Dq   512
#define Fq   2048
#define MF   (Bq*Sq)          // 2048 GEMM rows
#define FLAT (Sq*Dq)          // 524288 per-batch flat size (2^19)
#define TOT  (Bq*FLAT)        // 1048576
#define LAMv 1e-4f

// ---------------- scratch (no allocations allowed) ----------------
__device__ float g_xb[(size_t)MF*Fq];   // x@Wx + b1 (16MB)
__device__ float g_h [(size_t)MF*Fq];   // hidden (16MB)
__device__ float g_z [TOT];             // current z
__device__ float g_f [TOT];             // f(z)
__device__ float g_Gh[4][TOT];          // g history, circular
__device__ float g_Zh[4][TOT];          // z history, circular
__device__ float g_red[2*14];           // per-batch: 10 HTH (upper tri) + 4 HTy
__device__ float g_gamma[2*4];

// ======================= helpers =======================
__device__ __forceinline__ uint32_t smem_u32(const void* p){
    uint32_t a;
    asm("{ .reg .u64 t; cvta.to.shared.u64 t, %1; cvt.u32.u64 %0, t; }" : "=r"(a) : "l"(p));
    return a;
}
#define SWZ(o) ((o) ^ (((o) >> 3) & 0x70))

__device__ __forceinline__ void ldm4(uint32_t* r, uint32_t addr){
    asm volatile("ldmatrix.sync.aligned.m8n8.x4.shared.b16 {%0,%1,%2,%3}, [%4];"
        : "=r"(r[0]), "=r"(r[1]), "=r"(r[2]), "=r"(r[3]) : "r"(addr));
}
__device__ __forceinline__ void mma_bf16(float* c, const uint32_t* a, const uint32_t* b){
    asm volatile("mma.sync.aligned.m16n8k16.row.col.f32.bf16.bf16.f32 "
        "{%0,%1,%2,%3}, {%4,%5,%6,%7}, {%8,%9}, {%0,%1,%2,%3};"
        : "+f"(c[0]), "+f"(c[1]), "+f"(c[2]), "+f"(c[3])
        : "r"(a[0]), "r"(a[1]), "r"(a[2]), "r"(a[3]), "r"(b[0]), "r"(b[1]));
}

// ======================= split-bf16 mma.sync GEMM =======================
// C[128 x BN tile] = epilogue( A @ B )   A: [M x K] fp32 row-major (lda == K)
//                                         B: [K x N] fp32 row-major (ld == ldn)
// MODE 0: C = acc + bias[n]      MODE 1: C = tanh(acc + Dm[m][n])
// Split: acc = Ah@Bh + Ah@Bl + Al@Bh  (bf16 MMAs, fp32 register accumulators)
template<int BN, int MODE>
__global__ __launch_bounds__(256, 1) void mma_gemm(
    const float* __restrict__ A, const float* __restrict__ Bm,
    const float* __restrict__ bias, const float* __restrict__ Dm,
    float* __restrict__ C, int K, int ldn)
{
    constexpr int ASZ = 128 * 64 * 2;      // bf16 A tile (one split)
    constexpr int BSZ = BN  * 64 * 2;      // bf16 B tile (one split)
    constexpr int BUF = 2 * ASZ + 2 * BSZ; // hi+lo for A and B
    constexpr int NW4 = BN / 4;            // n4-groups in B loader
    constexpr int IT  = (8 * BN) / 256;    // B loader iterations
    constexpr int NT  = BN / 16;           // n8-tiles per warp (warp covers BN/2)

    extern __shared__ char dynraw[];
    char* dyn = (char*)(((uintptr_t)dynraw + 1023) & ~(uintptr_t)1023);

    const int tid  = threadIdx.x;
    const int wid  = tid >> 5;
    const int lane = tid & 31;
    const int m0w  = (wid & 3) * 32;           // warp row offset (4 warps in M)
    const int n0w  = (wid >> 2) * (BN / 2);    // warp col offset (2 warps in N)

    const float* Ablk = A  + (size_t)blockIdx.y * 128 * K;
    const float* Bblk = Bm + (size_t)blockIdx.x * BN;
    const int NS = K >> 6;

    float acc[2][NT][4];
#pragma unroll
    for (int mt = 0; mt < 2; mt++)
#pragma unroll
        for (int nt = 0; nt < NT; nt++)
#pragma unroll
            for (int v = 0; v < 4; v++) acc[mt][nt][v] = 0.f;

    // ---------- slab loaders ----------
    // A: 128 rows x 64 fp32 -> hi/lo bf16, SW128. 8 float4 per thread.
    // B: BN rows(n) x 64(k) transposed from gmem [k][n]. IT*2 float4 per thread.
    auto sts_slab = [&](const float4* pa, const float4* pb0, const float4* pb1,
                        char* buf) {
        char* bufAh = buf;
        char* bufAl = buf + ASZ;
        char* bufBh = buf + 2 * ASZ;
        char* bufBl = buf + 2 * ASZ + BSZ;
#pragma unroll
        for (int it = 0; it < 8; it++) {
            int f4  = tid + it * 256;
            int row = f4 >> 4;
            int c4  = (f4 & 15) << 2;
            float4 v = pa[it];
            __nv_bfloat162 h01 = __floats2bfloat162_rn(v.x, v.y);
            __nv_bfloat162 h23 = __floats2bfloat162_rn(v.z, v.w);
            __nv_bfloat162 l01 = __floats2bfloat162_rn(v.x - __bfloat162float(h01.x),
                                                       v.y - __bfloat162float(h01.y));
            __nv_bfloat162 l23 = __floats2bfloat162_rn(v.z - __bfloat162float(h23.x),
                                                       v.w - __bfloat162float(h23.y));
            uint32_t sw = SWZ((uint32_t)(row * 128 + c4 * 2));
            *(__nv_bfloat162*)(bufAh + sw)     = h01;
            *(__nv_bfloat162*)(bufAh + sw + 4) = h23;
            *(__nv_bfloat162*)(bufAl + sw)     = l01;
            *(__nv_bfloat162*)(bufAl + sw + 4) = l23;
        }
#pragma unroll
        for (int it = 0; it < IT; it++) {
            int idx = tid + it * 256;
            int kp  = idx / NW4;
            int n4  = (idx % NW4) << 2;
            int kk  = kp << 1;
            float4 v0 = pb0[it], v1 = pb1[it];
            const float* a0 = (const float*)&v0;
            const float* a1 = (const float*)&v1;
#pragma unroll
            for (int j = 0; j < 4; j++) {
                float x0 = a0[j], x1 = a1[j];
                __nv_bfloat162 hh = __floats2bfloat162_rn(x0, x1);
                __nv_bfloat162 ll = __floats2bfloat162_rn(x0 - __bfloat162float(hh.x),
                                                          x1 - __bfloat162float(hh.y));
                uint32_t sw = SWZ((uint32_t)((n4 + j) * 128 + kk * 2));
                *(__nv_bfloat162*)(bufBh + sw) = hh;
                *(__nv_bfloat162*)(bufBl + sw) = ll;
            }
        }
    };
    auto ldg_slab = [&](int s, float4* pa, float4* pb0, float4* pb1) {
        const float* Ap = Ablk + s * 64;
#pragma unroll
        for (int it = 0; it < 8; it++) {
            int f4  = tid + it * 256;
            int row = f4 >> 4;
            int c4  = (f4 & 15) << 2;
            pa[it] = *(const float4*)(Ap + (size_t)row * K + c4);
        }
#pragma unroll
        for (int it = 0; it < IT; it++) {
            int idx = tid + it * 256;
            int kp  = idx / NW4;
            int n4  = (idx % NW4) << 2;
            int kk  = kp << 1;
            const float* bp = Bblk + (size_t)(s * 64 + kk) * ldn + n4;
            pb0[it] = *(const float4*)bp;
            pb1[it] = *(const float4*)(bp + ldn);
        }
    };

    // ---------- prologue: slab 0 ----------
    {
        float4 pa[8], pb0[IT], pb1[IT];
        ldg_slab(0, pa, pb0, pb1);
        sts_slab(pa, pb0, pb1, dyn);
    }
    __syncthreads();

    // ---------- main loop ----------
    const int arow = lane & 15;
    const int brow = (lane & 7) | ((lane >> 1) & 8);
    const int asel = lane >> 4;          // 0/1 -> k chunk
    const int bsel = (lane >> 3) & 1;

    for (int s = 0; s < NS; s++) {
        const bool pf = (s + 1) < NS;
        float4 pa[8], pb0[IT], pb1[IT];
        if (pf) ldg_slab(s + 1, pa, pb0, pb1);

        char* buf = dyn + (s & 1) * BUF;
        const uint32_t bAh = smem_u32(buf);
        const uint32_t bAl = bAh + ASZ;
        const uint32_t bBh = bAh + 2 * ASZ;
        const uint32_t bBl = bBh + BSZ;

#pragma unroll
        for (int ks = 0; ks < 4; ks++) {
            uint32_t ah[2][4], al[2][4];
            const int achunk = (ks << 1) + asel;
#pragma unroll
            for (int mt = 0; mt < 2; mt++) {
                uint32_t off = SWZ((uint32_t)((m0w + mt * 16 + arow) * 128 + achunk * 16));
                ldm4(ah[mt], bAh + off);
                ldm4(al[mt], bAl + off);
            }
            uint32_t bh[NT][2], bl[NT][2];
            const int bchunk = (ks << 1) + bsel;
#pragma unroll
            for (int np = 0; np < NT / 2; np++) {
                uint32_t off = SWZ((uint32_t)((n0w + np * 16 + brow) * 128 + bchunk * 16));
                uint32_t r[4];
                ldm4(r, bBh + off);
                bh[2*np][0] = r[0]; bh[2*np][1] = r[1];
                bh[2*np+1][0] = r[2]; bh[2*np+1][1] = r[3];
                ldm4(r, bBl + off);
                bl[2*np][0] = r[0]; bl[2*np][1] = r[1];
                bl[2*np+1][0] = r[2]; bl[2*np+1][1] = r[3];
            }
#pragma unroll
            for (int mt = 0; mt < 2; mt++)
#pragma unroll
                for (int nt = 0; nt < NT; nt++) {
                    mma_bf16(acc[mt][nt], ah[mt], bh[nt]);
                    mma_bf16(acc[mt][nt], ah[mt], bl[nt]);
                    mma_bf16(acc[mt][nt], al[mt], bh[nt]);
                }
        }

        if (pf) sts_slab(pa, pb0, pb1, dyn + ((s + 1) & 1) * BUF);
        __syncthreads();
    }

    // ---------- epilogue ----------
#pragma unroll
    for (int mt = 0; mt < 2; mt++) {
        const int gm = blockIdx.y * 128 + m0w + mt * 16 + (lane >> 2);
#pragma unroll
        for (int nt = 0; nt < NT; nt++) {
            const int gn = blockIdx.x * BN + n0w + nt * 8 + ((lane & 3) << 1);
            float2 r0, r1;
            if (MODE == 0) {
                float2 bv = *(const float2*)(bias + gn);
                r0.x = acc[mt][nt][0] + bv.x;  r0.y = acc[mt][nt][1] + bv.y;
                r1.x = acc[mt][nt][2] + bv.x;  r1.y = acc[mt][nt][3] + bv.y;
            } else {
                float2 d0 = *(const float2*)(Dm + (size_t)gm * ldn + gn);
                float2 d1 = *(const float2*)(Dm + (size_t)(gm + 8) * ldn + gn);
                r0.x = tanhf(acc[mt][nt][0] + d0.x);  r0.y = tanhf(acc[mt][nt][1] + d0.y);
                r1.x = tanhf(acc[mt][nt][2] + d1.x);  r1.y = tanhf(acc[mt][nt][3] + d1.y);
            }
            *(float2*)(C + (size_t)gm * ldn + gn)       = r0;
            *(float2*)(C + (size_t)(gm + 8) * ldn + gn) = r1;
        }
    }
}

// ---------------- iteration 0: h = tanh(xb) (z==0, skip GEMM1) ----------------
__global__ void tanh_map(const float* __restrict__ src, float* __restrict__ dst)
{
    int i = blockIdx.x * blockDim.x + threadIdx.x;
    float4 v = ((const float4*)src)[i];
    v.x = tanhf(v.x); v.y = tanhf(v.y); v.z = tanhf(v.z); v.w = tanhf(v.w);
    ((float4*)dst)[i] = v;
}

// ---------------- i < M: z_new = f; record history ----------------
__global__ void upd_simple(const float* __restrict__ f, float* __restrict__ z,
                           float* __restrict__ dst, int sw)
{
    int i = blockIdx.x * blockDim.x + threadIdx.x;
    float4 fv = ((const float4*)f)[i];
    float4 zv = ((const float4*)z)[i];
    float4 gv;
    gv.x = fv.x - zv.x; gv.y = fv.y - zv.y; gv.z = fv.z - zv.z; gv.w = fv.w - zv.w;
    ((float4*)g_Gh[sw])[i] = gv;
    ((float4*)g_Zh[sw])[i] = zv;
    ((float4*)dst)[i] = fv;
}

// ---------------- Anderson: HTH/HTy reduction ----------------
__global__ void reduce_k(const float* __restrict__ f, const float* __restrict__ z,
                         int s1, int s2, int s3, int s4)
{
    int b = blockIdx.y;
    int base = b * (FLAT / 4);
    const float4* fp = (const float4*)f + base;
    const float4* zp = (const float4*)z + base;
    const float4* h1 = (const float4*)g_Gh[s1] + base;
    const float4* h2 = (const float4*)g_Gh[s2] + base;
    const float4* h3 = (const float4*)g_Gh[s3] + base;
    const float4* h4 = (const float4*)g_Gh[s4] + base;

    float acc[14];
#pragma unroll
    for (int v = 0; v < 14; v++) acc[v] = 0.f;

    int n4 = FLAT / 4;
    for (int i = blockIdx.x * blockDim.x + threadIdx.x; i < n4;
         i += gridDim.x * blockDim.x) {
        float4 fv = fp[i], zv = zp[i];
        float4 a1 = h1[i], a2 = h2[i], a3 = h3[i], a4 = h4[i];
        const float* fa = (const float*)&fv; const float* za = (const float*)&zv;
        const float* p1 = (const float*)&a1; const float* p2 = (const float*)&a2;
        const float* p3 = (const float*)&a3; const float* p4 = (const float*)&a4;
#pragma unroll
        for (int c = 0; c < 4; c++) {
            float g  = fa[c] - za[c];
            float d0 = g - p1[c];
            float d1 = g - p2[c];
            float d2 = g - p3[c];
            float d3 = g - p4[c];
            acc[0] += d0 * d0; acc[1] += d0 * d1; acc[2] += d0 * d2; acc[3] += d0 * d3;
            acc[4] += d1 * d1; acc[5] += d1 * d2; acc[6] += d1 * d3;
            acc[7] += d2 * d2; acc[8] += d2 * d3; acc[9] += d3 * d3;
            acc[10] += d0 * g; acc[11] += d1 * g; acc[12] += d2 * g; acc[13] += d3 * g;
        }
    }
#pragma unroll
    for (int v = 0; v < 14; v++)
#pragma unroll
        for (int o = 16; o > 0; o >>= 1)
            acc[v] += __shfl_down_sync(0xffffffffu, acc[v], o);

    __shared__ float sm[8][14];
    int w = threadIdx.x / 32, lane = threadIdx.x % 32;
    if (lane == 0) {
#pragma unroll
        for (int v = 0; v < 14; v++) sm[w][v] = acc[v];
    }
    __syncthreads();
    if (threadIdx.x < 14) {
        float s = 0.f;
#pragma unroll
        for (int w2 = 0; w2 < 8; w2++) s += sm[w2][threadIdx.x];
        atomicAdd(&g_red[b * 14 + threadIdx.x], s);
    }
}

// ---------------- 4x4 Schur-complement solve (replicates reference exactly) ----------------
__device__ __forceinline__ void inv2x2d(const float m[4], float o[4])
{
    float invDet = 1.f / (m[0] * m[3] - m[1] * m[2] + 1e-6f);
    o[0] =  m[3] * invDet; o[1] = -m[1] * invDet;
    o[2] = -m[2] * invDet; o[3] =  m[0] * invDet;
}
__device__ __forceinline__ void mul2x2d(const float a[4], const float b[4], float o[4])
{
    o[0] = a[0] * b[0] + a[1] * b[2]; o[1] = a[0] * b[1] + a[1] * b[3];
    o[2] = a[2] * b[0] + a[3] * b[2]; o[3] = a[2] * b[1] + a[3] * b[3];
}

__global__ void solve_k()
{
    int b = threadIdx.x;
    if (b >= 2) return;
    const float* r = &g_red[b * 14];
    float H[4][4];
    H[0][0] = r[0] + LAMv; H[0][1] = r[1];        H[0][2] = r[2];        H[0][3] = r[3];
    H[1][0] = r[1];        H[1][1] = r[4] + LAMv; H[1][2] = r[5];        H[1][3] = r[6];
    H[2][0] = r[2];        H[2][1] = r[5];        H[2][2] = r[7] + LAMv; H[2][3] = r[8];
    H[3][0] = r[3];        H[3][1] = r[6];        H[3][2] = r[8];        H[3][3] = r[9] + LAMv;
    float y[4] = { r[10], r[11], r[12], r[13] };

    float A_[4] = { H[0][0], H[0][1], H[1][0], H[1][1] };
    float Bb[4] = { H[0][2], H[0][3], H[1][2], H[1][3] };
    float C_[4] = { H[2][0], H[2][1], H[3][0], H[3][1] };
    float Dd[4] = { H[2][2], H[2][3], H[3][2], H[3][3] };

    float Ai[4];   inv2x2d(A_, Ai);
    float CAi[4];  mul2x2d(C_, Ai, CAi);
    float CAiB[4]; mul2x2d(CAi, Bb, CAiB);
    float Sch[4]  = { Dd[0] - CAiB[0], Dd[1] - CAiB[1], Dd[2] - CAiB[2], Dd[3] - CAiB[3] };
    float Si[4];   inv2x2d(Sch, Si);
    float SiCAi[4]; mul2x2d(Si, CAi, SiCAi);
    float AiB[4];   mul2x2d(Ai, Bb, AiB);
    float t11[4];   mul2x2d(AiB, SiCAi, t11);
    float b11[4] = { Ai[0] + t11[0], Ai[1] + t11[1], Ai[2] + t11[2], Ai[3] + t11[3] };
    float b12[4];   mul2x2d(AiB, Si, b12);
    b12[0] = -b12[0]; b12[1] = -b12[1]; b12[2] = -b12[2]; b12[3] = -b12[3];

    float inv[4][4] = {
        { b11[0],  b11[1],  b12[0],  b12[1] },
        { b11[2],  b11[3],  b12[2],  b12[3] },
        { -SiCAi[0], -SiCAi[1], Si[0], Si[1] },
        { -SiCAi[2], -SiCAi[3], Si[2], Si[3] }
    };
#pragma unroll
    for (int j = 0; j < 4; j++)
        g_gamma[b * 4 + j] = inv[j][0] * y[0] + inv[j][1] * y[1]
                           + inv[j][2] * y[2] + inv[j][3] * y[3];
}

// ---------------- Anderson mixed update ----------------
__global__ void upd_anderson(const float* __restrict__ f, float* __restrict__ z,
                             float* __restrict__ dst,
                             int s1, int s2, int s3, int s4, int sw)
{
    int i = blockIdx.x * blockDim.x + threadIdx.x;
    int b = i >> 17;
    float ga0 = g_gamma[b * 4 + 0];
    float ga1 = g_gamma[b * 4 + 1];
    float ga2 = g_gamma[b * 4 + 2];
    float ga3 = g_gamma[b * 4 + 3];

    float4 fv = ((const float4*)f)[i];
    float4 zv = ((const float4*)z)[i];
    float4 G1 = ((const float4*)g_Gh[s1])[i];
    float4 G2 = ((const float4*)g_Gh[s2])[i];
    float4 G3 = ((const float4*)g_Gh[s3])[i];
    float4 G4 = ((const float4*)g_Gh[s4])[i];
    float4 Z1 = ((const float4*)g_Zh[s1])[i];
    float4 Z2 = ((const float4*)g_Zh[s2])[i];
    float4 Z3 = ((const float4*)g_Zh[s3])[i];
    float4 Z4 = ((const float4*)g_Zh[s4])[i];

    float4 gv, ov;
    float* fa = (float*)&fv;  float* za = (float*)&zv;
    float* g1 = (float*)&G1;  float* g2 = (float*)&G2;
    float* g3 = (float*)&G3;  float* g4 = (float*)&G4;
    float* z1 = (float*)&Z1;  float* z2 = (float*)&Z2;
    float* z3 = (float*)&Z3;  float* z4 = (float*)&Z4;
    float* gva = (float*)&gv; float* ova = (float*)&ov;

#pragma unroll
    for (int c = 0; c < 4; c++) {
        float zc = za[c];
        float g  = fa[c] - zc;
        float corr = ga0 * ((zc - z1[c]) + (g - g1[c]))
                   + ga1 * ((zc - z2[c]) + (g - g2[c]))
                   + ga2 * ((zc - z3[c]) + (g - g3[c]))
                   + ga3 * ((zc - z4[c]) + (g - g4[c]));
        gva[c] = g;
        ova[c] = zc + g - corr;
    }
    ((float4*)g_Gh[sw])[i] = gv;
    ((float4*)g_Zh[sw])[i] = zv;
    ((float4*)dst)[i] = ov;
}

// ---------------- launcher ----------------
extern "C" void kernel_launch(void* const* d_in, const int* in_sizes, int n_in,
                              void* d_out, int out_size)
{
    (void)in_sizes; (void)n_in; (void)out_size;
    const float* x  = (const float*)d_in[0];
    const float* W1 = (const float*)d_in[1];
    const float* Wx = (const float*)d_in[2];
    const float* b1 = (const float*)d_in[3];
    const float* W2 = (const float*)d_in[4];
    const float* b2 = (const float*)d_in[5];
    float* out = (float*)d_out;

    float *xb, *h, *z, *f, *red;
    cudaGetSymbolAddress((void**)&xb,  g_xb);
    cudaGetSymbolAddress((void**)&h,   g_h);
    cudaGetSymbolAddress((void**)&z,   g_z);
    cudaGetSymbolAddress((void**)&f,   g_f);
    cudaGetSymbolAddress((void**)&red, g_red);

    // dynamic smem: 2 buffers of (2*ASZ + 2*BSZ) + 1KB alignment slack
    const int DYN128 = 2 * (2 * 128*64*2 + 2 * 128*64*2) + 1024;  // 132 KB
    const int DYN64  = 2 * (2 * 128*64*2 + 2 *  64*64*2) + 1024;  //  99 KB
    cudaFuncSetAttribute(mma_gemm<128,0>, cudaFuncAttributeMaxDynamicSharedMemorySize, DYN128);
    cudaFuncSetAttribute(mma_gemm<128,1>, cudaFuncAttributeMaxDynamicSharedMemorySize, DYN128);
    cudaFuncSetAttribute(mma_gemm<64,0>,  cudaFuncAttributeMaxDynamicSharedMemorySize, DYN64);

    cudaMemsetAsync(z, 0, (size_t)TOT * sizeof(float));

    dim3 g1(Fq / 128, MF / 128);   // 16 x 16 : N=2048 GEMMs
    dim3 g2(Dq / 64,  MF / 128);   // 8 x 16  : N=512 GEMM (one full wave)

    // xb = x @ Wx + b1   (once)
    mma_gemm<128,0><<<g1, 256, DYN128>>>(x, Wx, b1, nullptr, xb, Dq, Fq);

    const int upd_blocks = TOT / 4 / 256;
    for (int i = 0; i < 12; i++) {
        // h = tanh(z @ W1 + xb)
        if (i == 0)
            tanh_map<<<(size_t)MF * Fq / 4 / 256, 256>>>(xb, h);   // z == 0
        else
            mma_gemm<128,1><<<g1, 256, DYN128>>>(z, W1, nullptr, xb, h, Dq, Fq);
        // f = h @ W2 + b2
        mma_gemm<64,0><<<g2, 256, DYN64>>>(h, W2, b2, nullptr, f, Fq, Dq);

        float* dst = (i == 11) ? out : z;
        if (i < 5) {
            upd_simple<<<upd_blocks, 256>>>(f, z, dst, i & 3);
        } else {
            cudaMemsetAsync(red, 0, 28 * sizeof(float));
            reduce_k<<<dim3(128, 2), 256>>>(f, z, (i - 1) & 3, (i - 2) & 3,
                                            (i - 3) & 3, (i - 4) & 3);
            solve_k<<<1, 32>>>();
            upd_anderson<<<upd_blocks, 256>>>(f, z, dst, (i - 1) & 3, (i - 2) & 3,
                                              (i - 3) & 3, (i - 4) & 3, i & 3);
        }
    }
}

// round 5
// speedup vs baseline: 2.8200x; 1.5782x over previous
#include <cuda_runtime.h>
#include <cuda_bf16.h>
#include <math.h>
#include <stdint.h>

// Problem constants
#define Bq   2
#define Sq   1024
#define Dq   512
#define Fq   2048
#define MF   (Bq*Sq)          // 2048 GEMM rows
#define FLAT (Sq*Dq)          // 524288 per-batch flat size (2^19)
#define TOT  (Bq*FLAT)        // 1048576
#define LAMv 1e-4f

// ---------------- scratch (no allocations allowed) ----------------
__device__ float g_xb[(size_t)MF*Fq];   // x@Wx + b1 (16MB)
__device__ float g_z [TOT];             // current z (fp32, for Anderson math)
__device__ float g_f [TOT];             // f(z)
__device__ float g_Gh[4][TOT];          // g history, circular
__device__ float g_Zh[4][TOT];          // z history, circular
__device__ float g_red[2*14];           // per-batch: 10 HTH (upper tri) + 4 HTy
__device__ float g_gamma[2*4];

// bf16 hi/lo planes (error-compensated split operands)
__device__ __nv_bfloat16 g_W1T[2][(size_t)Fq*Dq];  // [N=2048][K=512]
__device__ __nv_bfloat16 g_WxT[2][(size_t)Fq*Dq];  // [2048][512]
__device__ __nv_bfloat16 g_W2T[2][(size_t)Dq*Fq];  // [512][2048]
__device__ __nv_bfloat16 g_xp [2][TOT];            // x   [2048][512]
__device__ __nv_bfloat16 g_zp [2][TOT];            // z   [2048][512]
__device__ __nv_bfloat16 g_hp [2][(size_t)MF*Fq];  // h   [2048][2048]

// ======================= helpers =======================
__device__ __forceinline__ uint32_t smem_u32(const void* p){
    uint32_t a;
    asm("{ .reg .u64 t; cvta.to.shared.u64 t, %1; cvt.u32.u64 %0, t; }" : "=r"(a) : "l"(p));
    return a;
}
#define SWZ(o) ((o) ^ (((o) >> 3) & 0x70))

__device__ __forceinline__ void ldm4(uint32_t* r, uint32_t addr){
    asm volatile("ldmatrix.sync.aligned.m8n8.x4.shared.b16 {%0,%1,%2,%3}, [%4];"
        : "=r"(r[0]), "=r"(r[1]), "=r"(r[2]), "=r"(r[3]) : "r"(addr));
}
__device__ __forceinline__ void mma_bf16(float* c, const uint32_t* a, const uint32_t* b){
    asm volatile("mma.sync.aligned.m16n8k16.row.col.f32.bf16.bf16.f32 "
        "{%0,%1,%2,%3}, {%4,%5,%6,%7}, {%8,%9}, {%0,%1,%2,%3};"
        : "+f"(c[0]), "+f"(c[1]), "+f"(c[2]), "+f"(c[3])
        : "r"(a[0]), "r"(a[1]), "r"(a[2]), "r"(a[3]), "r"(b[0]), "r"(b[1]));
}
__device__ __forceinline__ void cpasync16(uint32_t dst, const void* src){
    asm volatile("cp.async.cg.shared.global [%0], [%1], 16;" :: "r"(dst), "l"(src));
}
__device__ __forceinline__ void cpcommit(){ asm volatile("cp.async.commit_group;" ::: "memory"); }
template<int N> __device__ __forceinline__ void cpwait(){
    asm volatile("cp.async.wait_group %0;" :: "n"(N) : "memory");
}
__device__ __forceinline__ __nv_bfloat162 split_hi(float a, float b){
    return __floats2bfloat162_rn(a, b);
}
__device__ __forceinline__ __nv_bfloat162 split_lo(float a, float b, __nv_bfloat162 h){
    return __floats2bfloat162_rn(a - __bfloat162float(h.x), b - __bfloat162float(h.y));
}

// ======================= pipelined split-bf16 mma.sync GEMM =======================
// A planes: [M x K] bf16 hi/lo, row-major.  B planes: [N x K] bf16 hi/lo, row-major.
// MODE 0: C fp32 = acc + bias[n]
// MODE 1: t = tanh(acc + Dm[m][n]); write Chp/Clp bf16 hi/lo planes (no fp32 C)
template<int BN, int MODE>
__global__ __launch_bounds__(256, 1) void gemm_p(
    const __nv_bfloat16* __restrict__ Ahp, const __nv_bfloat16* __restrict__ Alp,
    const __nv_bfloat16* __restrict__ Bhp, const __nv_bfloat16* __restrict__ Blp,
    const float* __restrict__ bias, const float* __restrict__ Dm,
    float* __restrict__ C,
    __nv_bfloat16* __restrict__ Chp, __nv_bfloat16* __restrict__ Clp,
    int K, int ldn)
{
    constexpr int ASTG = 128 * 64 * 2;         // one A plane per stage (16 KB)
    constexpr int BSTG = BN  * 64 * 2;         // one B plane per stage
    constexpr int STG  = 2 * ASTG + 2 * BSTG;  // stage size
    constexpr int BIT  = (BN * 8) / 256;       // B chunks per thread per plane
    constexpr int NT   = BN / 16;              // n8-tiles per warp

    extern __shared__ char dynraw[];
    char* dyn = (char*)(((uintptr_t)dynraw + 1023) & ~(uintptr_t)1023);

    const int tid  = threadIdx.x;
    const int wid  = tid >> 5;
    const int lane = tid & 31;
    const int m0w  = (wid & 3) * 32;
    const int n0w  = (wid >> 2) * (BN / 2);
    const int NS   = K >> 6;

    float acc[2][NT][4];
#pragma unroll
    for (int mt = 0; mt < 2; mt++)
#pragma unroll
        for (int nt = 0; nt < NT; nt++)
#pragma unroll
            for (int v = 0; v < 4; v++) acc[mt][nt][v] = 0.f;

    auto issue = [&](int s, int st){
        char* buf = dyn + st * STG;
        uint32_t ba = smem_u32(buf);
        const __nv_bfloat16* ap[2] = { Ahp, Alp };
#pragma unroll
        for (int p = 0; p < 2; p++)
#pragma unroll
            for (int it = 0; it < 4; it++) {
                int c = tid + it * 256;          // 0..1023
                int row = c >> 3, kc = c & 7;
                const void* src = ap[p] + (size_t)(blockIdx.y * 128 + row) * K + s * 64 + kc * 8;
                cpasync16(ba + p * ASTG + SWZ((uint32_t)(row * 128 + kc * 16)), src);
            }
        const __nv_bfloat16* bp[2] = { Bhp, Blp };
#pragma unroll
        for (int p = 0; p < 2; p++)
#pragma unroll
            for (int it = 0; it < BIT; it++) {
                int c = tid + it * 256;
                int row = c >> 3, kc = c & 7;
                const void* src = bp[p] + (size_t)(blockIdx.x * BN + row) * K + s * 64 + kc * 8;
                cpasync16(ba + 2 * ASTG + p * BSTG + SWZ((uint32_t)(row * 128 + kc * 16)), src);
            }
    };

    // prologue: 2 stages in flight
    issue(0, 0); cpcommit();
    issue(1, 1); cpcommit();

    const int arow = lane & 15;
    const int brow = (lane & 7) | ((lane >> 1) & 8);
    const int asel = lane >> 4;
    const int bsel = (lane >> 3) & 1;

    for (int s = 0; s < NS; s++) {
        const int st = s % 3;
        if (s + 2 < NS) issue(s + 2, (s + 2) % 3);
        cpcommit();
        cpwait<2>();                 // stage s landed
        __syncthreads();

        const uint32_t bAh = smem_u32(dyn + st * STG);
        const uint32_t bAl = bAh + ASTG;
        const uint32_t bBh = bAh + 2 * ASTG;
        const uint32_t bBl = bBh + BSTG;

#pragma unroll
        for (int ks = 0; ks < 4; ks++) {
            uint32_t ah[2][4], al[2][4];
            const int achunk = (ks << 1) + asel;
#pragma unroll
            for (int mt = 0; mt < 2; mt++) {
                uint32_t off = SWZ((uint32_t)((m0w + mt * 16 + arow) * 128 + achunk * 16));
                ldm4(ah[mt], bAh + off);
                ldm4(al[mt], bAl + off);
            }
            uint32_t bh[NT][2], bl[NT][2];
            const int bchunk = (ks << 1) + bsel;
#pragma unroll
            for (int np = 0; np < NT / 2; np++) {
                uint32_t off = SWZ((uint32_t)((n0w + np * 16 + brow) * 128 + bchunk * 16));
                uint32_t r[4];
                ldm4(r, bBh + off);
                bh[2*np][0] = r[0]; bh[2*np][1] = r[1];
                bh[2*np+1][0] = r[2]; bh[2*np+1][1] = r[3];
                ldm4(r, bBl + off);
                bl[2*np][0] = r[0]; bl[2*np][1] = r[1];
                bl[2*np+1][0] = r[2]; bl[2*np+1][1] = r[3];
            }
#pragma unroll
            for (int mt = 0; mt < 2; mt++)
#pragma unroll
                for (int nt = 0; nt < NT; nt++) {
                    mma_bf16(acc[mt][nt], ah[mt], bh[nt]);
                    mma_bf16(acc[mt][nt], ah[mt], bl[nt]);
                    mma_bf16(acc[mt][nt], al[mt], bh[nt]);
                }
        }
        __syncthreads();             // all reads done before stage reuse
    }

    // ---------- epilogue ----------
#pragma unroll
    for (int mt = 0; mt < 2; mt++) {
        const int gm = blockIdx.y * 128 + m0w + mt * 16 + (lane >> 2);
#pragma unroll
        for (int nt = 0; nt < NT; nt++) {
            const int gn = blockIdx.x * BN + n0w + nt * 8 + ((lane & 3) << 1);
            if (MODE == 0) {
                float2 bv = *(const float2*)(bias + gn);
                float2 r0, r1;
                r0.x = acc[mt][nt][0] + bv.x;  r0.y = acc[mt][nt][1] + bv.y;
                r1.x = acc[mt][nt][2] + bv.x;  r1.y = acc[mt][nt][3] + bv.y;
                *(float2*)(C + (size_t)gm * ldn + gn)       = r0;
                *(float2*)(C + (size_t)(gm + 8) * ldn + gn) = r1;
            } else {
                float2 d0 = *(const float2*)(Dm + (size_t)gm * ldn + gn);
                float2 d1 = *(const float2*)(Dm + (size_t)(gm + 8) * ldn + gn);
                float t0 = tanhf(acc[mt][nt][0] + d0.x);
                float t1 = tanhf(acc[mt][nt][1] + d0.y);
                float t2 = tanhf(acc[mt][nt][2] + d1.x);
                float t3 = tanhf(acc[mt][nt][3] + d1.y);
                __nv_bfloat162 h0 = split_hi(t0, t1);
                __nv_bfloat162 h1 = split_hi(t2, t3);
                *(__nv_bfloat162*)(Chp + (size_t)gm * ldn + gn)       = h0;
                *(__nv_bfloat162*)(Chp + (size_t)(gm + 8) * ldn + gn) = h1;
                *(__nv_bfloat162*)(Clp + (size_t)gm * ldn + gn)       = split_lo(t0, t1, h0);
                *(__nv_bfloat162*)(Clp + (size_t)(gm + 8) * ldn + gn) = split_lo(t2, t3, h1);
            }
        }
    }
}

// ---------------- one-time converters ----------------
// W [K x N] fp32 -> T hi/lo [N x K] bf16 (transposed)
__global__ void conv_wT(const float* __restrict__ W,
                        __nv_bfloat16* __restrict__ Th, __nv_bfloat16* __restrict__ Tl,
                        int K, int N)
{
    __shared__ float t[32][33];
    int n0 = blockIdx.x * 32, k0 = blockIdx.y * 32;
    int tx = threadIdx.x, ty = threadIdx.y;   // 32 x 8
#pragma unroll
    for (int r = 0; r < 32; r += 8)
        t[ty + r][tx] = W[(size_t)(k0 + ty + r) * N + n0 + tx];
    __syncthreads();
#pragma unroll
    for (int r = 0; r < 32; r += 8) {
        float v = t[tx][ty + r];
        __nv_bfloat16 hb = __float2bfloat16(v);
        size_t o = (size_t)(n0 + ty + r) * K + k0 + tx;
        Th[o] = hb;
        Tl[o] = __float2bfloat16(v - __bfloat162float(hb));
    }
}
// X fp32 -> planes (no transpose)
__global__ void conv_plane(const float* __restrict__ X,
                           __nv_bfloat16* __restrict__ Xh, __nv_bfloat16* __restrict__ Xl)
{
    int i = blockIdx.x * blockDim.x + threadIdx.x;
    float4 v = ((const float4*)X)[i];
    __nv_bfloat162 h01 = split_hi(v.x, v.y), h23 = split_hi(v.z, v.w);
    ((__nv_bfloat162*)Xh)[i*2]   = h01;
    ((__nv_bfloat162*)Xh)[i*2+1] = h23;
    ((__nv_bfloat162*)Xl)[i*2]   = split_lo(v.x, v.y, h01);
    ((__nv_bfloat162*)Xl)[i*2+1] = split_lo(v.z, v.w, h23);
}

// ---------------- iteration 0: h = tanh(xb) (z==0) ----------------
__global__ void tanh_map(const float* __restrict__ src,
                         __nv_bfloat16* __restrict__ Hh, __nv_bfloat16* __restrict__ Hl)
{
    int i = blockIdx.x * blockDim.x + threadIdx.x;
    float4 v = ((const float4*)src)[i];
    v.x = tanhf(v.x); v.y = tanhf(v.y); v.z = tanhf(v.z); v.w = tanhf(v.w);
    __nv_bfloat162 h01 = split_hi(v.x, v.y), h23 = split_hi(v.z, v.w);
    ((__nv_bfloat162*)Hh)[i*2]   = h01;
    ((__nv_bfloat162*)Hh)[i*2+1] = h23;
    ((__nv_bfloat162*)Hl)[i*2]   = split_lo(v.x, v.y, h01);
    ((__nv_bfloat162*)Hl)[i*2+1] = split_lo(v.z, v.w, h23);
}

// ---------------- i < M: z_new = f; record history; emit z planes ----------------
__global__ void upd_simple(const float* __restrict__ f, float* __restrict__ z,
                           float* __restrict__ dst, int sw)
{
    int i = blockIdx.x * blockDim.x + threadIdx.x;
    float4 fv = ((const float4*)f)[i];
    float4 zv = ((const float4*)z)[i];
    float4 gv;
    gv.x = fv.x - zv.x; gv.y = fv.y - zv.y; gv.z = fv.z - zv.z; gv.w = fv.w - zv.w;
    ((float4*)g_Gh[sw])[i] = gv;
    ((float4*)g_Zh[sw])[i] = zv;
    ((float4*)dst)[i] = fv;
    __nv_bfloat162 h01 = split_hi(fv.x, fv.y), h23 = split_hi(fv.z, fv.w);
    ((__nv_bfloat162*)g_zp[0])[i*2]   = h01;
    ((__nv_bfloat162*)g_zp[0])[i*2+1] = h23;
    ((__nv_bfloat162*)g_zp[1])[i*2]   = split_lo(fv.x, fv.y, h01);
    ((__nv_bfloat162*)g_zp[1])[i*2+1] = split_lo(fv.z, fv.w, h23);
}

// ---------------- Anderson: HTH/HTy reduction ----------------
__global__ void reduce_k(const float* __restrict__ f, const float* __restrict__ z,
                         int s1, int s2, int s3, int s4)
{
    int b = blockIdx.y;
    int base = b * (FLAT / 4);
    const float4* fp = (const float4*)f + base;
    const float4* zp = (const float4*)z + base;
    const float4* h1 = (const float4*)g_Gh[s1] + base;
    const float4* h2 = (const float4*)g_Gh[s2] + base;
    const float4* h3 = (const float4*)g_Gh[s3] + base;
    const float4* h4 = (const float4*)g_Gh[s4] + base;

    float acc[14];
#pragma unroll
    for (int v = 0; v < 14; v++) acc[v] = 0.f;

    int n4 = FLAT / 4;
    for (int i = blockIdx.x * blockDim.x + threadIdx.x; i < n4;
         i += gridDim.x * blockDim.x) {
        float4 fv = fp[i], zv = zp[i];
        float4 a1 = h1[i], a2 = h2[i], a3 = h3[i], a4 = h4[i];
        const float* fa = (const float*)&fv; const float* za = (const float*)&zv;
        const float* p1 = (const float*)&a1; const float* p2 = (const float*)&a2;
        const float* p3 = (const float*)&a3; const float* p4 = (const float*)&a4;
#pragma unroll
        for (int c = 0; c < 4; c++) {
            float g  = fa[c] - za[c];
            float d0 = g - p1[c];
            float d1 = g - p2[c];
            float d2 = g - p3[c];
            float d3 = g - p4[c];
            acc[0] += d0 * d0; acc[1] += d0 * d1; acc[2] += d0 * d2; acc[3] += d0 * d3;
            acc[4] += d1 * d1; acc[5] += d1 * d2; acc[6] += d1 * d3;
            acc[7] += d2 * d2; acc[8] += d2 * d3; acc[9] += d3 * d3;
            acc[10] += d0 * g; acc[11] += d1 * g; acc[12] += d2 * g; acc[13] += d3 * g;
        }
    }
#pragma unroll
    for (int v = 0; v < 14; v++)
#pragma unroll
        for (int o = 16; o > 0; o >>= 1)
            acc[v] += __shfl_down_sync(0xffffffffu, acc[v], o);

    __shared__ float sm[8][14];
    int w = threadIdx.x / 32, lane = threadIdx.x % 32;
    if (lane == 0) {
#pragma unroll
        for (int v = 0; v < 14; v++) sm[w][v] = acc[v];
    }
    __syncthreads();
    if (threadIdx.x < 14) {
        float s = 0.f;
#pragma unroll
        for (int w2 = 0; w2 < 8; w2++) s += sm[w2][threadIdx.x];
        atomicAdd(&g_red[b * 14 + threadIdx.x], s);
    }
}

// ---------------- 4x4 Schur-complement solve (replicates reference exactly) ----------------
__device__ __forceinline__ void inv2x2d(const float m[4], float o[4])
{
    float invDet = 1.f / (m[0] * m[3] - m[1] * m[2] + 1e-6f);
    o[0] =  m[3] * invDet; o[1] = -m[1] * invDet;
    o[2] = -m[2] * invDet; o[3] =  m[0] * invDet;
}
__device__ __forceinline__ void mul2x2d(const float a[4], const float b[4], float o[4])
{
    o[0] = a[0] * b[0] + a[1] * b[2]; o[1] = a[0] * b[1] + a[1] * b[3];
    o[2] = a[2] * b[0] + a[3] * b[2]; o[3] = a[2] * b[1] + a[3] * b[3];
}

__global__ void solve_k()
{
    int b = threadIdx.x;
    if (b >= 2) return;
    const float* r = &g_red[b * 14];
    float H[4][4];
    H[0][0] = r[0] + LAMv; H[0][1] = r[1];        H[0][2] = r[2];        H[0][3] = r[3];
    H[1][0] = r[1];        H[1][1] = r[4] + LAMv; H[1][2] = r[5];        H[1][3] = r[6];
    H[2][0] = r[2];        H[2][1] = r[5];        H[2][2] = r[7] + LAMv; H[2][3] = r[8];
    H[3][0] = r[3];        H[3][1] = r[6];        H[3][2] = r[8];        H[3][3] = r[9] + LAMv;
    float y[4] = { r[10], r[11], r[12], r[13] };

    float A_[4] = { H[0][0], H[0][1], H[1][0], H[1][1] };
    float Bb[4] = { H[0][2], H[0][3], H[1][2], H[1][3] };
    float C_[4] = { H[2][0], H[2][1], H[3][0], H[3][1] };
    float Dd[4] = { H[2][2], H[2][3], H[3][2], H[3][3] };

    float Ai[4];   inv2x2d(A_, Ai);
    float CAi[4];  mul2x2d(C_, Ai, CAi);
    float CAiB[4]; mul2x2d(CAi, Bb, CAiB);
    float Sch[4]  = { Dd[0] - CAiB[0], Dd[1] - CAiB[1], Dd[2] - CAiB[2], Dd[3] - CAiB[3] };
    float Si[4];   inv2x2d(Sch, Si);
    float SiCAi[4]; mul2x2d(Si, CAi, SiCAi);
    float AiB[4];   mul2x2d(Ai, Bb, AiB);
    float t11[4];   mul2x2d(AiB, SiCAi, t11);
    float b11[4] = { Ai[0] + t11[0], Ai[1] + t11[1], Ai[2] + t11[2], Ai[3] + t11[3] };
    float b12[4];   mul2x2d(AiB, Si, b12);
    b12[0] = -b12[0]; b12[1] = -b12[1]; b12[2] = -b12[2]; b12[3] = -b12[3];

    float inv[4][4] = {
        { b11[0],  b11[1],  b12[0],  b12[1] },
        { b11[2],  b11[3],  b12[2],  b12[3] },
        { -SiCAi[0], -SiCAi[1], Si[0], Si[1] },
        { -SiCAi[2], -SiCAi[3], Si[2], Si[3] }
    };
#pragma unroll
    for (int j = 0; j < 4; j++)
        g_gamma[b * 4 + j] = inv[j][0] * y[0] + inv[j][1] * y[1]
                           + inv[j][2] * y[2] + inv[j][3] * y[3];
}

// ---------------- Anderson mixed update (+ z planes) ----------------
__global__ void upd_anderson(const float* __restrict__ f, float* __restrict__ z,
                             float* __restrict__ dst,
                             int s1, int s2, int s3, int s4, int sw)
{
    int i = blockIdx.x * blockDim.x + threadIdx.x;
    int b = i >> 17;
    float ga0 = g_gamma[b * 4 + 0];
    float ga1 = g_gamma[b * 4 + 1];
    float ga2 = g_gamma[b * 4 + 2];
    float ga3 = g_gamma[b * 4 + 3];

    float4 fv = ((const float4*)f)[i];
    float4 zv = ((const float4*)z)[i];
    float4 G1 = ((const float4*)g_Gh[s1])[i];
    float4 G2 = ((const float4*)g_Gh[s2])[i];
    float4 G3 = ((const float4*)g_Gh[s3])[i];
    float4 G4 = ((const float4*)g_Gh[s4])[i];
    float4 Z1 = ((const float4*)g_Zh[s1])[i];
    float4 Z2 = ((const float4*)g_Zh[s2])[i];
    float4 Z3 = ((const float4*)g_Zh[s3])[i];
    float4 Z4 = ((const float4*)g_Zh[s4])[i];

    float4 gv, ov;
    float* fa = (float*)&fv;  float* za = (float*)&zv;
    float* g1 = (float*)&G1;  float* g2 = (float*)&G2;
    float* g3 = (float*)&G3;  float* g4 = (float*)&G4;
    float* z1 = (float*)&Z1;  float* z2 = (float*)&Z2;
    float* z3 = (float*)&Z3;  float* z4 = (float*)&Z4;
    float* gva = (float*)&gv; float* ova = (float*)&ov;

#pragma unroll
    for (int c = 0; c < 4; c++) {
        float zc = za[c];
        float g  = fa[c] - zc;
        float corr = ga0 * ((zc - z1[c]) + (g - g1[c]))
                   + ga1 * ((zc - z2[c]) + (g - g2[c]))
                   + ga2 * ((zc - z3[c]) + (g - g3[c]))
                   + ga3 * ((zc - z4[c]) + (g - g4[c]));
        gva[c] = g;
        ova[c] = zc + g - corr;
    }
    ((float4*)g_Gh[sw])[i] = gv;
    ((float4*)g_Zh[sw])[i] = zv;
    ((float4*)dst)[i] = ov;
    __nv_bfloat162 h01 = split_hi(ov.x, ov.y), h23 = split_hi(ov.z, ov.w);
    ((__nv_bfloat162*)g_zp[0])[i*2]   = h01;
    ((__nv_bfloat162*)g_zp[0])[i*2+1] = h23;
    ((__nv_bfloat162*)g_zp[1])[i*2]   = split_lo(ov.x, ov.y, h01);
    ((__nv_bfloat162*)g_zp[1])[i*2+1] = split_lo(ov.z, ov.w, h23);
}

// ---------------- launcher ----------------
extern "C" void kernel_launch(void* const* d_in, const int* in_sizes, int n_in,
                              void* d_out, int out_size)
{
    (void)in_sizes; (void)n_in; (void)out_size;
    const float* x  = (const float*)d_in[0];
    const float* W1 = (const float*)d_in[1];
    const float* Wx = (const float*)d_in[2];
    const float* b1 = (const float*)d_in[3];
    const float* W2 = (const float*)d_in[4];
    const float* b2 = (const float*)d_in[5];
    float* out = (float*)d_out;

    float *xb, *z, *f, *red;
    cudaGetSymbolAddress((void**)&xb,  g_xb);
    cudaGetSymbolAddress((void**)&z,   g_z);
    cudaGetSymbolAddress((void**)&f,   g_f);
    cudaGetSymbolAddress((void**)&red, g_red);
    __nv_bfloat16 *W1Th, *W1Tl, *WxTh, *WxTl, *W2Th, *W2Tl, *xh, *xl, *zh, *zl, *hh, *hl;
    cudaGetSymbolAddress((void**)&W1Th, g_W1T); W1Tl = W1Th + (size_t)Fq*Dq;
    cudaGetSymbolAddress((void**)&WxTh, g_WxT); WxTl = WxTh + (size_t)Fq*Dq;
    cudaGetSymbolAddress((void**)&W2Th, g_W2T); W2Tl = W2Th + (size_t)Dq*Fq;
    cudaGetSymbolAddress((void**)&xh,   g_xp);  xl   = xh   + TOT;
    cudaGetSymbolAddress((void**)&zh,   g_zp);  zl   = zh   + TOT;
    cudaGetSymbolAddress((void**)&hh,   g_hp);  hl   = hh   + (size_t)MF*Fq;

    const int DYN128 = 3 * (2*128*64*2 + 2*128*64*2) + 1024;   // 193 KB
    const int DYN64  = 3 * (2*128*64*2 + 2* 64*64*2) + 1024;   // 145 KB
    cudaFuncSetAttribute(gemm_p<128,0>, cudaFuncAttributeMaxDynamicSharedMemorySize, DYN128);
    cudaFuncSetAttribute(gemm_p<128,1>, cudaFuncAttributeMaxDynamicSharedMemorySize, DYN128);
    cudaFuncSetAttribute(gemm_p<64,0>,  cudaFuncAttributeMaxDynamicSharedMemorySize, DYN64);

    cudaMemsetAsync(z, 0, (size_t)TOT * sizeof(float));

    // one-time conversions
    dim3 tb(32, 8);
    conv_wT<<<dim3(Fq/32, Dq/32), tb>>>(W1, W1Th, W1Tl, Dq, Fq);
    conv_wT<<<dim3(Fq/32, Dq/32), tb>>>(Wx, WxTh, WxTl, Dq, Fq);
    conv_wT<<<dim3(Dq/32, Fq/32), tb>>>(W2, W2Th, W2Tl, Fq, Dq);
    conv_plane<<<TOT/4/256, 256>>>(x, xh, xl);

    dim3 g1(Fq / 128, MF / 128);   // 16 x 16
    dim3 g2(Dq / 64,  MF / 128);   // 8 x 16

    // xb = x @ Wx + b1
    gemm_p<128,0><<<g1, 256, DYN128>>>(xh, xl, WxTh, WxTl, b1, nullptr, xb, nullptr, nullptr, Dq, Fq);

    const int upd_blocks = TOT / 4 / 256;
    for (int i = 0; i < 12; i++) {
        // h = tanh(z @ W1 + xb)  -> bf16 hi/lo planes
        if (i == 0)
            tanh_map<<<(size_t)MF * Fq / 4 / 256, 256>>>(xb, hh, hl);
        else
            gemm_p<128,1><<<g1, 256, DYN128>>>(zh, zl, W1Th, W1Tl, nullptr, xb, nullptr, hh, hl, Dq, Fq);
        // f = h @ W2 + b2
        gemm_p<64,0><<<g2, 256, DYN64>>>(hh, hl, W2Th, W2Tl, b2, nullptr, f, nullptr, nullptr, Fq, Dq);

        float* dst = (i == 11) ? out : z;
        if (i < 5) {
            upd_simple<<<upd_blocks, 256>>>(f, z, dst, i & 3);
        } else {
            cudaMemsetAsync(red, 0, 28 * sizeof(float));
            reduce_k<<<dim3(128, 2), 256>>>(f, z, (i - 1) & 3, (i - 2) & 3,
                                            (i - 3) & 3, (i - 4) & 3);
            solve_k<<<1, 32>>>();
            upd_anderson<<<upd_blocks, 256>>>(f, z, dst, (i - 1) & 3, (i - 2) & 3,
                                              (i - 3) & 3, (i - 4) & 3, i & 3);
        }
    }
}